// round 9
// baseline (speedup 1.0000x reference)
#include <cuda_runtime.h>
#include <cstdint>

#define TT   256
#define BB   32
#define NTHR 256
#define NBLK 128
#define SA   36                  // act row stride (floats)
#define REGF (96 * SA)           // one region: rows 0-63 h1 | 64-95 h2

// shared layout (float offsets)
#define OFF_W1 0                 // [96][256] split-half permuted (rows 0-31 x-part, 32-95 h1-part)
#define OFF_W2 24576             // [96][128] split-half permuted
#define OFF_B1 36864             // [256]
#define OFF_B2 37120             // [128]
#define OFF_X  37248             // x triple buffer: [3][32][SA]
#define OFF_R  (OFF_X + 3 * 32 * SA)     // 2 regions + pad
#define SMEM_FLOATS (OFF_R + 2 * REGF + 2 * SA)
#define SMEM_BYTES  (SMEM_FLOATS * 4)    // ~191 KB

__device__ __forceinline__ void fma2(uint64_t& d, uint64_t a, uint64_t b) {
    asm("fma.rn.f32x2 %0, %1, %2, %0;" : "+l"(d) : "l"(a), "l"(b));
}
__device__ __forceinline__ float2 u2f2(uint64_t u) {
    float2 f; asm("mov.b64 {%0, %1}, %2;" : "=f"(f.x), "=f"(f.y) : "l"(u)); return f;
}
__device__ __forceinline__ uint64_t f2u2(float x, float y) {
    uint64_t u; asm("mov.b64 %0, {%1, %2};" : "=l"(u) : "f"(x), "f"(y)); return u;
}
__device__ __forceinline__ float mtanh(float x) {
    float y; asm("tanh.approx.f32 %0, %1;" : "=f"(y) : "f"(x)); return y;
}
__device__ __forceinline__ float sigf(float x) {
    return fmaf(0.5f, mtanh(0.5f * x), 0.5f);
}

__device__ __forceinline__ void cellup(uint64_t gi, uint64_t gf, uint64_t gg, uint64_t go,
                                       uint64_t& cst, float2& h) {
    float2 iv = u2f2(gi), fv = u2f2(gf), gv = u2f2(gg), ov = u2f2(go), cv = u2f2(cst);
    float c0 = sigf(fv.x) * cv.x + sigf(iv.x) * mtanh(gv.x);
    float c1 = sigf(fv.y) * cv.y + sigf(iv.y) * mtanh(gv.y);
    cst = f2u2(c0, c1);
    h.x = sigf(ov.x) * mtanh(c0);
    h.y = sigf(ov.y) * mtanh(c1);
}

__device__ __forceinline__ void l1_fma(uint64_t (&acc)[8][4],
                                       const ulonglong2& w0, const ulonglong2& w1,
                                       const float4& a0, const float4& a1) {
    float av[8] = {a0.x, a0.y, a0.z, a0.w, a1.x, a1.y, a1.z, a1.w};
    #pragma unroll
    for (int b = 0; b < 8; b++) {
        uint64_t ad = f2u2(av[b], av[b]);
        fma2(acc[b][0], ad, w0.x); fma2(acc[b][1], ad, w0.y);
        fma2(acc[b][2], ad, w1.x); fma2(acc[b][3], ad, w1.y);
    }
}
__device__ __forceinline__ void l2_fma(uint64_t (&acc)[4][4],
                                       const ulonglong2& w0, const ulonglong2& w1,
                                       const float4& a0) {
    float av[4] = {a0.x, a0.y, a0.z, a0.w};
    #pragma unroll
    for (int b = 0; b < 4; b++) {
        uint64_t ad = f2u2(av[b], av[b]);
        fma2(acc[b][0], ad, w0.x); fma2(acc[b][1], ad, w0.y);
        fma2(acc[b][2], ad, w1.x); fma2(acc[b][3], ad, w1.y);
    }
}

// 32-k x-part accumulation (L1), double-buffered
__device__ __forceinline__ void l1_xpart(uint64_t (&acc)[8][4],
                                         const float* __restrict__ wp,
                                         const float* __restrict__ ap) {
    ulonglong2 w0a = *(const ulonglong2*)wp;
    ulonglong2 w1a = *(const ulonglong2*)(wp + 128);
    float4 a0a = *(const float4*)ap;
    float4 a1a = *(const float4*)(ap + 4);
    #pragma unroll 2
    for (int k = 0; k < 32; k += 2) {
        ulonglong2 w0b = *(const ulonglong2*)(wp + 256);
        ulonglong2 w1b = *(const ulonglong2*)(wp + 384);
        float4 a0b = *(const float4*)(ap + SA);
        float4 a1b = *(const float4*)(ap + SA + 4);
        l1_fma(acc, w0a, w1a, a0a, a1a);
        w0a = *(const ulonglong2*)(wp + 512);   // overrun safe (rows 32-33 exist)
        w1a = *(const ulonglong2*)(wp + 640);
        a0a = *(const float4*)(ap + 2 * SA);
        a1a = *(const float4*)(ap + 2 * SA + 4);
        l1_fma(acc, w0b, w1b, a0b, a1b);
        wp += 512; ap += 2 * SA;
    }
}

__global__ void __launch_bounds__(NTHR, 1)
lstm_pipe_kernel(const float* __restrict__ x,
                 const float* __restrict__ Wih1, const float* __restrict__ Whh1,
                 const float* __restrict__ bih1, const float* __restrict__ bhh1,
                 const float* __restrict__ Wih2, const float* __restrict__ Whh2,
                 const float* __restrict__ bih2, const float* __restrict__ bhh2,
                 const float* __restrict__ Whead, const float* __restrict__ bhead,
                 float* __restrict__ out)
{
    extern __shared__ float sm[];
    const int tid = threadIdx.x;

    // ---- weights (same permutation as R7) ----
    for (int idx = tid; idx < 96 * 256; idx += NTHR) {
        int k = idx >> 8, c = idx & 255;
        int half = c >> 7, r = c & 127;
        int jp = r >> 2, g2 = (r >> 1) & 1, jl = r & 1;
        int gate = half * 2 + g2;
        int grow = gate * 64 + jp * 2 + jl;
        sm[OFF_W1 + idx] = (k < 32) ? Wih1[grow * 32 + k] : Whh1[grow * 64 + (k - 32)];
    }
    for (int idx = tid; idx < 96 * 128; idx += NTHR) {
        int k = idx >> 7, c = idx & 127;
        int half = c >> 6, r = c & 63;
        int jp = r >> 2, g2 = (r >> 1) & 1, jl = r & 1;
        int gate = half * 2 + g2;
        int grow = gate * 32 + jp * 2 + jl;
        sm[OFF_W2 + idx] = (k < 64) ? Wih2[grow * 64 + k] : Whh2[grow * 32 + (k - 64)];
    }
    {
        int c = tid, jp = c >> 3, g = (c >> 1) & 3, jl = c & 1;
        int grow = g * 64 + jp * 2 + jl;
        sm[OFF_B1 + c] = bih1[grow] + bhh1[grow];
    }
    if (tid < 128) {
        int c = tid, jp = c >> 3, g = (c >> 1) & 3, jl = c & 1;
        int grow = g * 32 + jp * 2 + jl;
        sm[OFF_B2 + c] = bih2[grow] + bhh2[grow];
    }
    for (int idx = tid; idx < 2 * REGF + 2 * SA; idx += NTHR) sm[OFF_R + idx] = 0.0f;
    // x[0] -> xb[0], x[1] -> xb[1]
    if (tid < 128) {
        int xb = tid >> 2, xq = tid & 3;
        const float* xg = x + ((size_t)(blockIdx.x * BB + xb) * TT) * 32 + xq * 8;
        int f0 = xq * 8;
        #pragma unroll
        for (int t = 0; t < 2; t++) {
            float4 v0 = *(const float4*)(xg + (size_t)t * 32);
            float4 v1 = *(const float4*)(xg + (size_t)t * 32 + 4);
            float* d = sm + OFF_X + t * (32 * SA);
            float vv[8] = {v0.x, v0.y, v0.z, v0.w, v1.x, v1.y, v1.z, v1.w};
            #pragma unroll
            for (int c = 0; c < 8; c++) d[(f0 + c) * SA + xb] = vv[c];
        }
    }
    __syncthreads();

    if (tid < 128) {
        // ================= LAYER-1 warps =================
        const int jp = tid & 31;
        const int bt = tid >> 5;
        uint64_t bias[4];
        {
            ulonglong2 b01 = *(const ulonglong2*)(sm + OFF_B1 + jp * 8);
            ulonglong2 b23 = *(const ulonglong2*)(sm + OFF_B1 + jp * 8 + 4);
            bias[0] = b01.x; bias[1] = b01.y; bias[2] = b23.x; bias[3] = b23.y;
        }
        uint64_t c1s[8] = {0,0,0,0,0,0,0,0};
        const float* wb_x = sm + OFF_W1 + jp * 4;              // rows 0-31 (x weights)
        const float* wb_h = sm + OFF_W1 + 32 * 256 + jp * 4;   // rows 32-95 (h1 weights)

        // prologue: acc = bias + x-part(step 0)
        uint64_t acc[8][4];
        #pragma unroll
        for (int b = 0; b < 8; b++) {
            acc[b][0] = bias[0]; acc[b][1] = bias[1];
            acc[b][2] = bias[2]; acc[b][3] = bias[3];
        }
        l1_xpart(acc, wb_x, sm + OFF_X + 8 * bt);

        for (int s = 0; s <= TT; s++) {
            if (s < TT) {
                const float* rr = sm + OFF_R + (s & 1) * REGF;
                float* wrg = sm + OFF_R + ((s + 1) & 1) * REGF;

                // h1-part: 64 k over h1[s-1] (rows 0-63 of rr)
                const float* wp = wb_h;
                const float* ap = rr + 8 * bt;
                ulonglong2 w0a = *(const ulonglong2*)wp;
                ulonglong2 w1a = *(const ulonglong2*)(wp + 128);
                float4 a0a = *(const float4*)ap;
                float4 a1a = *(const float4*)(ap + 4);
                #pragma unroll 2
                for (int k = 0; k < 64; k += 2) {
                    ulonglong2 w0b = *(const ulonglong2*)(wp + 256);
                    ulonglong2 w1b = *(const ulonglong2*)(wp + 384);
                    float4 a0b = *(const float4*)(ap + SA);
                    float4 a1b = *(const float4*)(ap + SA + 4);
                    l1_fma(acc, w0a, w1a, a0a, a1a);
                    w0a = *(const ulonglong2*)(wp + 512);   // overrun -> W2 region, safe
                    w1a = *(const ulonglong2*)(wp + 640);
                    a0a = *(const float4*)(ap + 2 * SA);
                    a1a = *(const float4*)(ap + 2 * SA + 4);
                    l1_fma(acc, w0b, w1b, a0b, a1b);
                    wp += 512; ap += 2 * SA;
                }

                float2 hv[8];
                #pragma unroll
                for (int b = 0; b < 8; b++)
                    cellup(acc[b][0], acc[b][1], acc[b][2], acc[b][3], c1s[b], hv[b]);

                // h1[s] -> wrg rows 2jp, 2jp+1
                int j0 = 2 * jp;
                *(float4*)&wrg[j0 * SA + 8 * bt]           = make_float4(hv[0].x, hv[1].x, hv[2].x, hv[3].x);
                *(float4*)&wrg[j0 * SA + 8 * bt + 4]       = make_float4(hv[4].x, hv[5].x, hv[6].x, hv[7].x);
                *(float4*)&wrg[(j0 + 1) * SA + 8 * bt]     = make_float4(hv[0].y, hv[1].y, hv[2].y, hv[3].y);
                *(float4*)&wrg[(j0 + 1) * SA + 8 * bt + 4] = make_float4(hv[4].y, hv[5].y, hv[6].y, hv[7].y);

                // x-part for step s+1 (independent of cellup -> interleaves with MUFU tail)
                if (s <= TT - 2) {
                    #pragma unroll
                    for (int b = 0; b < 8; b++) {
                        acc[b][0] = bias[0]; acc[b][1] = bias[1];
                        acc[b][2] = bias[2]; acc[b][3] = bias[3];
                    }
                    const float* xbuf = sm + OFF_X + ((s + 1) % 3) * (32 * SA);
                    l1_xpart(acc, wb_x, xbuf + 8 * bt);
                }
            }
            __syncthreads();
        }
    } else {
        // ================= LAYER-2 warps (+ x prefetch 2 ahead) =================
        const int u = tid - 128;
        const int lane = u & 31;
        const int jp = lane & 15;
        const int b0 = (u >> 5) * 8 + (lane >> 4) * 4;
        const int xb = u >> 2, xq = u & 3;
        const float* xg0 = x + ((size_t)(blockIdx.x * BB + xb) * TT) * 32 + xq * 8;
        uint64_t bias[4];
        {
            ulonglong2 b01 = *(const ulonglong2*)(sm + OFF_B2 + jp * 8);
            ulonglong2 b23 = *(const ulonglong2*)(sm + OFF_B2 + jp * 8 + 4);
            bias[0] = b01.x; bias[1] = b01.y; bias[2] = b23.x; bias[3] = b23.y;
        }
        uint64_t c2s[4] = {0,0,0,0};
        const float* wbase = sm + OFF_W2 + jp * 4;

        for (int s = 0; s <= TT; s++) {
            float4 pv0, pv1;
            const bool dopf = (s + 2 < TT);
            if (dopf) {
                const float* xg = xg0 + (size_t)(s + 2) * 32;
                pv0 = *(const float4*)xg;
                pv1 = *(const float4*)(xg + 4);
            }
            const float* rr = sm + OFF_R + (s & 1) * REGF;
            float* wrg = sm + OFF_R + ((s + 1) & 1) * REGF;

            if (s >= 1) {
                uint64_t acc[4][4];
                #pragma unroll
                for (int b = 0; b < 4; b++) {
                    acc[b][0] = bias[0]; acc[b][1] = bias[1];
                    acc[b][2] = bias[2]; acc[b][3] = bias[3];
                }
                // fused h1[s-1] (rows 0-63) + h2[s-2] (rows 64-95)
                const float* wp = wbase;
                const float* ap = rr + b0;
                ulonglong2 w0a = *(const ulonglong2*)wp;
                ulonglong2 w1a = *(const ulonglong2*)(wp + 64);
                float4 a0a = *(const float4*)ap;
                #pragma unroll 2
                for (int k = 0; k < 96; k += 2) {
                    ulonglong2 w0b = *(const ulonglong2*)(wp + 128);
                    ulonglong2 w1b = *(const ulonglong2*)(wp + 192);
                    float4 a0b = *(const float4*)(ap + SA);
                    l2_fma(acc, w0a, w1a, a0a);
                    w0a = *(const ulonglong2*)(wp + 256);   // overrun safe
                    w1a = *(const ulonglong2*)(wp + 320);
                    a0a = *(const float4*)(ap + 2 * SA);
                    l2_fma(acc, w0b, w1b, a0b);
                    wp += 256; ap += 2 * SA;
                }

                float2 hv[4];
                #pragma unroll
                for (int b = 0; b < 4; b++)
                    cellup(acc[b][0], acc[b][1], acc[b][2], acc[b][3], c2s[b], hv[b]);

                // h2[s-1] -> wrg rows 64+2jp, 65+2jp
                float* hd = wrg + 64 * SA;
                int j0 = 2 * jp;
                *(float4*)&hd[j0 * SA + b0]       = make_float4(hv[0].x, hv[1].x, hv[2].x, hv[3].x);
                *(float4*)&hd[(j0 + 1) * SA + b0] = make_float4(hv[0].y, hv[1].y, hv[2].y, hv[3].y);
            }
            if (dopf) {
                float* d = sm + OFF_X + ((s + 2) % 3) * (32 * SA);
                int f0 = xq * 8;
                float vv[8] = {pv0.x, pv0.y, pv0.z, pv0.w, pv1.x, pv1.y, pv1.z, pv1.w};
                #pragma unroll
                for (int c = 0; c < 8; c++) d[(f0 + c) * SA + xb] = vv[c];
            }
            __syncthreads();
        }
    }

    // ---- head: h2[TT-1] in region 1, rows 64-95 ----
    if (tid < 96) {
        int b = tid / 3, n = tid % 3;
        const float* h2p = sm + OFF_R + REGF + 64 * SA;
        float accv = bhead[n];
        #pragma unroll
        for (int j = 0; j < 32; j++)
            accv += h2p[j * SA + b] * Whead[n * 32 + j];
        out[(size_t)(blockIdx.x * BB + b) * 3 + n] = accv;
    }
}

extern "C" void kernel_launch(void* const* d_in, const int* in_sizes, int n_in,
                              void* d_out, int out_size) {
    (void)in_sizes; (void)n_in; (void)out_size;
    const float* x     = (const float*)d_in[0];
    const float* Wih1  = (const float*)d_in[1];
    const float* Whh1  = (const float*)d_in[2];
    const float* bih1  = (const float*)d_in[3];
    const float* bhh1  = (const float*)d_in[4];
    const float* Wih2  = (const float*)d_in[5];
    const float* Whh2  = (const float*)d_in[6];
    const float* bih2  = (const float*)d_in[7];
    const float* bhh2  = (const float*)d_in[8];
    const float* Whead = (const float*)d_in[9];
    const float* bhead = (const float*)d_in[10];
    float* out = (float*)d_out;

    cudaFuncSetAttribute(lstm_pipe_kernel,
                         cudaFuncAttributeMaxDynamicSharedMemorySize, SMEM_BYTES);
    lstm_pipe_kernel<<<NBLK, NTHR, SMEM_BYTES>>>(
        x, Wih1, Whh1, bih1, bhh1, Wih2, Whh2, bih2, bhh2, Whead, bhead, out);
}

// round 10
// speedup vs baseline: 1.0202x; 1.0202x over previous
#include <cuda_runtime.h>
#include <cstdint>

#define TT   256
#define BB   32
#define NTHR 256
#define NBLK 128
#define SA   36                  // act row stride (floats), 16B-aligned, bank-staggered
#define REGF (128 * SA)          // one region: rows 0-31 x | 32-95 h1 | 96-127 h2

// shared layout (float offsets)
#define OFF_W1 0                 // [96][256] split-half permuted
#define OFF_W2 24576             // [96][128] split-half permuted
#define OFF_B1 36864             // [256]
#define OFF_B2 37120             // [128]
#define OFF_R  37248             // 2 regions + pad
#define SMEM_FLOATS (OFF_R + 2 * REGF + 2 * SA)
#define SMEM_BYTES  (SMEM_FLOATS * 4)   // ~186 KB

__device__ __forceinline__ void fma2(uint64_t& d, uint64_t a, uint64_t b) {
    asm("fma.rn.f32x2 %0, %1, %2, %0;" : "+l"(d) : "l"(a), "l"(b));
}
__device__ __forceinline__ float2 u2f2(uint64_t u) {
    float2 f; asm("mov.b64 {%0, %1}, %2;" : "=f"(f.x), "=f"(f.y) : "l"(u)); return f;
}
__device__ __forceinline__ uint64_t f2u2(float x, float y) {
    uint64_t u; asm("mov.b64 %0, {%1, %2};" : "=l"(u) : "f"(x), "f"(y)); return u;
}
// HW MUFU.TANH (sm_75+)
__device__ __forceinline__ float mtanh(float x) {
    float y; asm("tanh.approx.f32 %0, %1;" : "=f"(y) : "f"(x)); return y;
}
__device__ __forceinline__ float sigf(float x) {
    return fmaf(0.5f, mtanh(0.5f * x), 0.5f);
}

__device__ __forceinline__ void cellup(uint64_t gi, uint64_t gf, uint64_t gg, uint64_t go,
                                       uint64_t& cst, float2& h) {
    float2 iv = u2f2(gi), fv = u2f2(gf), gv = u2f2(gg), ov = u2f2(go), cv = u2f2(cst);
    float c0 = sigf(fv.x) * cv.x + sigf(iv.x) * mtanh(gv.x);
    float c1 = sigf(fv.y) * cv.y + sigf(iv.y) * mtanh(gv.y);
    cst = f2u2(c0, c1);
    h.x = sigf(ov.x) * mtanh(c0);
    h.y = sigf(ov.y) * mtanh(c1);
}

__device__ __forceinline__ void l1_fma(uint64_t (&acc)[8][4],
                                       const ulonglong2& w0, const ulonglong2& w1,
                                       const float4& a0, const float4& a1) {
    float av[8] = {a0.x, a0.y, a0.z, a0.w, a1.x, a1.y, a1.z, a1.w};
    #pragma unroll
    for (int b = 0; b < 8; b++) {
        uint64_t ad = f2u2(av[b], av[b]);
        fma2(acc[b][0], ad, w0.x); fma2(acc[b][1], ad, w0.y);
        fma2(acc[b][2], ad, w1.x); fma2(acc[b][3], ad, w1.y);
    }
}
__device__ __forceinline__ void l2_fma(uint64_t (&acc)[4][4],
                                       const ulonglong2& w0, const ulonglong2& w1,
                                       const float4& a0) {
    float av[4] = {a0.x, a0.y, a0.z, a0.w};
    #pragma unroll
    for (int b = 0; b < 4; b++) {
        uint64_t ad = f2u2(av[b], av[b]);
        fma2(acc[b][0], ad, w0.x); fma2(acc[b][1], ad, w0.y);
        fma2(acc[b][2], ad, w1.x); fma2(acc[b][3], ad, w1.y);
    }
}

__global__ void __launch_bounds__(NTHR, 1)
lstm_pipe_kernel(const float* __restrict__ x,
                 const float* __restrict__ Wih1, const float* __restrict__ Whh1,
                 const float* __restrict__ bih1, const float* __restrict__ bhh1,
                 const float* __restrict__ Wih2, const float* __restrict__ Whh2,
                 const float* __restrict__ bih2, const float* __restrict__ bhh2,
                 const float* __restrict__ Whead, const float* __restrict__ bhead,
                 float* __restrict__ out)
{
    extern __shared__ float sm[];
    const int tid = threadIdx.x;

    // ---- weights: L1 row k = [i/f half: jp*4][g/o half at +128], j-pair (2jp, 2jp+1)
    for (int idx = tid; idx < 96 * 256; idx += NTHR) {
        int k = idx >> 8, c = idx & 255;
        int half = c >> 7, r = c & 127;
        int jp = r >> 2, g2 = (r >> 1) & 1, jl = r & 1;
        int gate = half * 2 + g2;
        int grow = gate * 64 + jp * 2 + jl;
        sm[OFF_W1 + idx] = (k < 32) ? Wih1[grow * 32 + k] : Whh1[grow * 64 + (k - 32)];
    }
    for (int idx = tid; idx < 96 * 128; idx += NTHR) {
        int k = idx >> 7, c = idx & 127;
        int half = c >> 6, r = c & 63;
        int jp = r >> 2, g2 = (r >> 1) & 1, jl = r & 1;
        int gate = half * 2 + g2;
        int grow = gate * 32 + jp * 2 + jl;
        sm[OFF_W2 + idx] = (k < 64) ? Wih2[grow * 64 + k] : Whh2[grow * 32 + (k - 64)];
    }
    {   // biases in acc order: jp*8 + gate*2 + jl
        int c = tid, jp = c >> 3, g = (c >> 1) & 3, jl = c & 1;
        int grow = g * 64 + jp * 2 + jl;
        sm[OFF_B1 + c] = bih1[grow] + bhh1[grow];
    }
    if (tid < 128) {
        int c = tid, jp = c >> 3, g = (c >> 1) & 3, jl = c & 1;
        int grow = g * 32 + jp * 2 + jl;
        sm[OFF_B2 + c] = bih2[grow] + bhh2[grow];
    }
    // zero both regions + pad
    for (int idx = tid; idx < 2 * REGF + 2 * SA; idx += NTHR) sm[OFF_R + idx] = 0.0f;
    __syncthreads();
    // x[0] -> region0 rows 0..31
    if (tid < 128) {
        int xb = tid >> 2, xq = tid & 3;
        const float* xg = x + ((size_t)(blockIdx.x * BB + xb) * TT) * 32 + xq * 8;
        float4 v0 = *(const float4*)xg;
        float4 v1 = *(const float4*)(xg + 4);
        float* d = sm + OFF_R;
        int f0 = xq * 8;
        float vv[8] = {v0.x, v0.y, v0.z, v0.w, v1.x, v1.y, v1.z, v1.w};
        #pragma unroll
        for (int c = 0; c < 8; c++) d[(f0 + c) * SA + xb] = vv[c];
    }
    __syncthreads();

    if (tid < 128) {
        // ================= LAYER-1 warps =================
        const int jp = tid & 31;
        const int bt = tid >> 5;
        uint64_t bias[4];
        {
            ulonglong2 b01 = *(const ulonglong2*)(sm + OFF_B1 + jp * 8);
            ulonglong2 b23 = *(const ulonglong2*)(sm + OFF_B1 + jp * 8 + 4);
            bias[0] = b01.x; bias[1] = b01.y; bias[2] = b23.x; bias[3] = b23.y;
        }
        uint64_t c1s[8] = {0,0,0,0,0,0,0,0};
        const float* wbase = sm + OFF_W1 + jp * 4;

        for (int s = 0; s <= TT; s++) {
            if (s < TT) {
                const float* rr = sm + OFF_R + (s & 1) * REGF;
                float* wrg = sm + OFF_R + ((s + 1) & 1) * REGF;

                uint64_t acc[8][4];
                #pragma unroll
                for (int b = 0; b < 8; b++) {
                    acc[b][0] = bias[0]; acc[b][1] = bias[1];
                    acc[b][2] = bias[2]; acc[b][3] = bias[3];
                }
                // fused x+h1 stream, prefetch distance 2 (k+2, k+3 staged)
                const float* wp = wbase;
                const float* ap = rr + 8 * bt;
                ulonglong2 w0a = *(const ulonglong2*)wp;
                ulonglong2 w1a = *(const ulonglong2*)(wp + 128);
                float4 a0a = *(const float4*)ap;
                float4 a1a = *(const float4*)(ap + 4);
                ulonglong2 w0b = *(const ulonglong2*)(wp + 256);
                ulonglong2 w1b = *(const ulonglong2*)(wp + 384);
                float4 a0b = *(const float4*)(ap + SA);
                float4 a1b = *(const float4*)(ap + SA + 4);
                #pragma unroll 2
                for (int k = 0; k < 96; k += 2) {
                    ulonglong2 w0c = *(const ulonglong2*)(wp + 512);   // overruns land in W2 (in-bounds)
                    ulonglong2 w1c = *(const ulonglong2*)(wp + 640);
                    float4 a0c = *(const float4*)(ap + 2 * SA);        // act overrun rows 96-97 exist
                    float4 a1c = *(const float4*)(ap + 2 * SA + 4);
                    ulonglong2 w0d = *(const ulonglong2*)(wp + 768);
                    ulonglong2 w1d = *(const ulonglong2*)(wp + 896);
                    float4 a0d = *(const float4*)(ap + 3 * SA);
                    float4 a1d = *(const float4*)(ap + 3 * SA + 4);
                    l1_fma(acc, w0a, w1a, a0a, a1a);
                    l1_fma(acc, w0b, w1b, a0b, a1b);
                    w0a = w0c; w1a = w1c; a0a = a0c; a1a = a1c;
                    w0b = w0d; w1b = w1d; a0b = a0d; a1b = a1d;
                    wp += 512; ap += 2 * SA;
                }

                float2 hv[8];
                #pragma unroll
                for (int b = 0; b < 8; b++)
                    cellup(acc[b][0], acc[b][1], acc[b][2], acc[b][3], c1s[b], hv[b]);

                // h1[s] -> write region rows 32+2jp, 33+2jp
                float* hd = wrg + 32 * SA;
                int j0 = 2 * jp;
                *(float4*)&hd[j0 * SA + 8 * bt]           = make_float4(hv[0].x, hv[1].x, hv[2].x, hv[3].x);
                *(float4*)&hd[j0 * SA + 8 * bt + 4]       = make_float4(hv[4].x, hv[5].x, hv[6].x, hv[7].x);
                *(float4*)&hd[(j0 + 1) * SA + 8 * bt]     = make_float4(hv[0].y, hv[1].y, hv[2].y, hv[3].y);
                *(float4*)&hd[(j0 + 1) * SA + 8 * bt + 4] = make_float4(hv[4].y, hv[5].y, hv[6].y, hv[7].y);
            }
            __syncthreads();
        }
    } else {
        // ================= LAYER-2 warps (+ x prefetch) =================
        const int u = tid - 128;
        const int lane = u & 31;
        const int jp = lane & 15;
        const int b0 = (u >> 5) * 8 + (lane >> 4) * 4;
        const int xb = u >> 2, xq = u & 3;
        const float* xg0 = x + ((size_t)(blockIdx.x * BB + xb) * TT) * 32 + xq * 8;
        uint64_t bias[4];
        {
            ulonglong2 b01 = *(const ulonglong2*)(sm + OFF_B2 + jp * 8);
            ulonglong2 b23 = *(const ulonglong2*)(sm + OFF_B2 + jp * 8 + 4);
            bias[0] = b01.x; bias[1] = b01.y; bias[2] = b23.x; bias[3] = b23.y;
        }
        uint64_t c2s[4] = {0,0,0,0};
        const float* wbase = sm + OFF_W2 + jp * 4;

        for (int s = 0; s <= TT; s++) {
            float4 pv0, pv1;
            const bool dopf = (s + 1 < TT);
            if (dopf) {
                const float* xg = xg0 + (size_t)(s + 1) * 32;
                pv0 = *(const float4*)xg;
                pv1 = *(const float4*)(xg + 4);
            }
            const float* rr = sm + OFF_R + (s & 1) * REGF;
            float* wrg = sm + OFF_R + ((s + 1) & 1) * REGF;

            if (s >= 1) {
                uint64_t acc[4][4];
                #pragma unroll
                for (int b = 0; b < 4; b++) {
                    acc[b][0] = bias[0]; acc[b][1] = bias[1];
                    acc[b][2] = bias[2]; acc[b][3] = bias[3];
                }
                // fused h1(s-1)+h2(s-2) stream, prefetch distance 2
                const float* wp = wbase;
                const float* ap = rr + 32 * SA + b0;
                ulonglong2 w0a = *(const ulonglong2*)wp;
                ulonglong2 w1a = *(const ulonglong2*)(wp + 64);
                float4 a0a = *(const float4*)ap;
                ulonglong2 w0b = *(const ulonglong2*)(wp + 128);
                ulonglong2 w1b = *(const ulonglong2*)(wp + 192);
                float4 a0b = *(const float4*)(ap + SA);
                #pragma unroll 2
                for (int k = 0; k < 96; k += 2) {
                    ulonglong2 w0c = *(const ulonglong2*)(wp + 256);   // overruns land in bias region (in-bounds)
                    ulonglong2 w1c = *(const ulonglong2*)(wp + 320);
                    float4 a0c = *(const float4*)(ap + 2 * SA);        // act overrun rows 128-129 = pad
                    ulonglong2 w0d = *(const ulonglong2*)(wp + 384);
                    ulonglong2 w1d = *(const ulonglong2*)(wp + 448);
                    float4 a0d = *(const float4*)(ap + 3 * SA);
                    l2_fma(acc, w0a, w1a, a0a);
                    l2_fma(acc, w0b, w1b, a0b);
                    w0a = w0c; w1a = w1c; a0a = a0c;
                    w0b = w0d; w1b = w1d; a0b = a0d;
                    wp += 256; ap += 2 * SA;
                }

                float2 hv[4];
                #pragma unroll
                for (int b = 0; b < 4; b++)
                    cellup(acc[b][0], acc[b][1], acc[b][2], acc[b][3], c2s[b], hv[b]);

                // h2[s-1] -> write region rows 96+2jp, 97+2jp
                float* hd = wrg + 96 * SA;
                int j0 = 2 * jp;
                *(float4*)&hd[j0 * SA + b0]       = make_float4(hv[0].x, hv[1].x, hv[2].x, hv[3].x);
                *(float4*)&hd[(j0 + 1) * SA + b0] = make_float4(hv[0].y, hv[1].y, hv[2].y, hv[3].y);
            }
            if (dopf) {
                float* d = wrg;   // x(s+1) -> write region rows 0..31
                int f0 = xq * 8;
                float vv[8] = {pv0.x, pv0.y, pv0.z, pv0.w, pv1.x, pv1.y, pv1.z, pv1.w};
                #pragma unroll
                for (int c = 0; c < 8; c++) d[(f0 + c) * SA + xb] = vv[c];
            }
            __syncthreads();
        }
    }

    // ---- head: h2[T-1] in region 1, rows 96..127 ----
    if (tid < 96) {
        int b = tid / 3, n = tid % 3;
        const float* h2p = sm + OFF_R + REGF + 96 * SA;
        float accv = bhead[n];
        #pragma unroll
        for (int j = 0; j < 32; j++)
            accv += h2p[j * SA + b] * Whead[n * 32 + j];
        out[(size_t)(blockIdx.x * BB + b) * 3 + n] = accv;
    }
}

extern "C" void kernel_launch(void* const* d_in, const int* in_sizes, int n_in,
                              void* d_out, int out_size) {
    (void)in_sizes; (void)n_in; (void)out_size;
    const float* x     = (const float*)d_in[0];
    const float* Wih1  = (const float*)d_in[1];
    const float* Whh1  = (const float*)d_in[2];
    const float* bih1  = (const float*)d_in[3];
    const float* bhh1  = (const float*)d_in[4];
    const float* Wih2  = (const float*)d_in[5];
    const float* Whh2  = (const float*)d_in[6];
    const float* bih2  = (const float*)d_in[7];
    const float* bhh2  = (const float*)d_in[8];
    const float* Whead = (const float*)d_in[9];
    const float* bhead = (const float*)d_in[10];
    float* out = (float*)d_out;

    cudaFuncSetAttribute(lstm_pipe_kernel,
                         cudaFuncAttributeMaxDynamicSharedMemorySize, SMEM_BYTES);
    lstm_pipe_kernel<<<NBLK, NTHR, SMEM_BYTES>>>(
        x, Wih1, Whh1, bih1, bhh1, Wih2, Whh2, bih2, bhh2, Whead, bhead, out);
}

// round 11
// speedup vs baseline: 1.0663x; 1.0452x over previous
#include <cuda_runtime.h>
#include <cstdint>

#define TT   256
#define BB   32
#define NTHR 256
#define NBLK 128
#define SA   36                  // act row stride (floats), 16B-aligned, bank-staggered
#define REGF (128 * SA)          // one region: rows 0-31 x | 32-95 h1 | 96-127 h2

// shared layout (float offsets)
#define OFF_W1 0                 // [96][256] split-half permuted
#define OFF_W2 24576             // [96][128] split-half permuted
#define OFF_B1 36864             // [256]
#define OFF_B2 37120             // [128]
#define OFF_R  37248             // 2 regions + pad
#define SMEM_FLOATS (OFF_R + 2 * REGF + 2 * SA)
#define SMEM_BYTES  (SMEM_FLOATS * 4)   // ~186 KB

__device__ __forceinline__ void fma2(uint64_t& d, uint64_t a, uint64_t b) {
    asm("fma.rn.f32x2 %0, %1, %2, %0;" : "+l"(d) : "l"(a), "l"(b));
}
__device__ __forceinline__ float2 u2f2(uint64_t u) {
    float2 f; asm("mov.b64 {%0, %1}, %2;" : "=f"(f.x), "=f"(f.y) : "l"(u)); return f;
}
__device__ __forceinline__ uint64_t f2u2(float x, float y) {
    uint64_t u; asm("mov.b64 %0, {%1, %2};" : "=l"(u) : "f"(x), "f"(y)); return u;
}
// HW MUFU.TANH (sm_75+)
__device__ __forceinline__ float mtanh(float x) {
    float y; asm("tanh.approx.f32 %0, %1;" : "=f"(y) : "f"(x)); return y;
}
__device__ __forceinline__ float sigf(float x) {
    return fmaf(0.5f, mtanh(0.5f * x), 0.5f);
}

__device__ __forceinline__ void cellup(uint64_t gi, uint64_t gf, uint64_t gg, uint64_t go,
                                       uint64_t& cst, float2& h) {
    float2 iv = u2f2(gi), fv = u2f2(gf), gv = u2f2(gg), ov = u2f2(go), cv = u2f2(cst);
    float c0 = sigf(fv.x) * cv.x + sigf(iv.x) * mtanh(gv.x);
    float c1 = sigf(fv.y) * cv.y + sigf(iv.y) * mtanh(gv.y);
    cst = f2u2(c0, c1);
    h.x = sigf(ov.x) * mtanh(c0);
    h.y = sigf(ov.y) * mtanh(c1);
}

__device__ __forceinline__ void l1_fma(uint64_t (&acc)[8][4],
                                       const ulonglong2& w0, const ulonglong2& w1,
                                       const float4& a0, const float4& a1) {
    float av[8] = {a0.x, a0.y, a0.z, a0.w, a1.x, a1.y, a1.z, a1.w};
    #pragma unroll
    for (int b = 0; b < 8; b++) {
        uint64_t ad = f2u2(av[b], av[b]);
        fma2(acc[b][0], ad, w0.x); fma2(acc[b][1], ad, w0.y);
        fma2(acc[b][2], ad, w1.x); fma2(acc[b][3], ad, w1.y);
    }
}
__device__ __forceinline__ void l2_fma(uint64_t (&acc)[4][4],
                                       const ulonglong2& w0, const ulonglong2& w1,
                                       const float4& a0) {
    float av[4] = {a0.x, a0.y, a0.z, a0.w};
    #pragma unroll
    for (int b = 0; b < 4; b++) {
        uint64_t ad = f2u2(av[b], av[b]);
        fma2(acc[b][0], ad, w0.x); fma2(acc[b][1], ad, w0.y);
        fma2(acc[b][2], ad, w1.x); fma2(acc[b][3], ad, w1.y);
    }
}

__global__ void __launch_bounds__(NTHR, 1)
lstm_pipe_kernel(const float* __restrict__ x,
                 const float* __restrict__ Wih1, const float* __restrict__ Whh1,
                 const float* __restrict__ bih1, const float* __restrict__ bhh1,
                 const float* __restrict__ Wih2, const float* __restrict__ Whh2,
                 const float* __restrict__ bih2, const float* __restrict__ bhh2,
                 const float* __restrict__ Whead, const float* __restrict__ bhead,
                 float* __restrict__ out)
{
    extern __shared__ float sm[];
    const int tid = threadIdx.x;

    // ---- weights: L1 row k = [i/f half: jp*4][g/o half at +128], j-pair (2jp, 2jp+1)
    for (int idx = tid; idx < 96 * 256; idx += NTHR) {
        int k = idx >> 8, c = idx & 255;
        int half = c >> 7, r = c & 127;
        int jp = r >> 2, g2 = (r >> 1) & 1, jl = r & 1;
        int gate = half * 2 + g2;
        int grow = gate * 64 + jp * 2 + jl;
        sm[OFF_W1 + idx] = (k < 32) ? Wih1[grow * 32 + k] : Whh1[grow * 64 + (k - 32)];
    }
    for (int idx = tid; idx < 96 * 128; idx += NTHR) {
        int k = idx >> 7, c = idx & 127;
        int half = c >> 6, r = c & 63;
        int jp = r >> 2, g2 = (r >> 1) & 1, jl = r & 1;
        int gate = half * 2 + g2;
        int grow = gate * 32 + jp * 2 + jl;
        sm[OFF_W2 + idx] = (k < 64) ? Wih2[grow * 64 + k] : Whh2[grow * 32 + (k - 64)];
    }
    {   // biases in acc order: jp*8 + gate*2 + jl
        int c = tid, jp = c >> 3, g = (c >> 1) & 3, jl = c & 1;
        int grow = g * 64 + jp * 2 + jl;
        sm[OFF_B1 + c] = bih1[grow] + bhh1[grow];
    }
    if (tid < 128) {
        int c = tid, jp = c >> 3, g = (c >> 1) & 3, jl = c & 1;
        int grow = g * 32 + jp * 2 + jl;
        sm[OFF_B2 + c] = bih2[grow] + bhh2[grow];
    }
    // zero both regions + pad
    for (int idx = tid; idx < 2 * REGF + 2 * SA; idx += NTHR) sm[OFF_R + idx] = 0.0f;
    __syncthreads();
    // x[0] -> region0 rows 0..31
    if (tid < 128) {
        int xb = tid >> 2, xq = tid & 3;
        const float* xg = x + ((size_t)(blockIdx.x * BB + xb) * TT) * 32 + xq * 8;
        float4 v0 = *(const float4*)xg;
        float4 v1 = *(const float4*)(xg + 4);
        float* d = sm + OFF_R;
        int f0 = xq * 8;
        float vv[8] = {v0.x, v0.y, v0.z, v0.w, v1.x, v1.y, v1.z, v1.w};
        #pragma unroll
        for (int c = 0; c < 8; c++) d[(f0 + c) * SA + xb] = vv[c];
    }
    __syncthreads();

    if (tid < 128) {
        // ================= LAYER-1 warps =================
        // Warp w owns j-pairs [8w, 8w+8); within warp, 4 lanes share a jp and
        // split the 32 batches into groups of 8. Weight row per warp-k = 8
        // distinct 16B chunks = 128B -> 1 wavefront per LDS.128 (was 4).
        const int lane = tid & 31;
        const int wd   = tid >> 5;
        const int jp = wd * 8 + (lane >> 2);   // 0..31
        const int bt = lane & 3;               // batches 8*bt .. 8*bt+7
        uint64_t bias[4];
        {
            ulonglong2 b01 = *(const ulonglong2*)(sm + OFF_B1 + jp * 8);
            ulonglong2 b23 = *(const ulonglong2*)(sm + OFF_B1 + jp * 8 + 4);
            bias[0] = b01.x; bias[1] = b01.y; bias[2] = b23.x; bias[3] = b23.y;
        }
        uint64_t c1s[8] = {0,0,0,0,0,0,0,0};
        const float* wbase = sm + OFF_W1 + jp * 4;

        for (int s = 0; s <= TT; s++) {
            if (s < TT) {
                const float* rr = sm + OFF_R + (s & 1) * REGF;
                float* wrg = sm + OFF_R + ((s + 1) & 1) * REGF;

                uint64_t acc[8][4];
                #pragma unroll
                for (int b = 0; b < 8; b++) {
                    acc[b][0] = bias[0]; acc[b][1] = bias[1];
                    acc[b][2] = bias[2]; acc[b][3] = bias[3];
                }
                // fused x+h1 stream, double-buffered (distance 1, best measured)
                const float* wp = wbase;
                const float* ap = rr + 8 * bt;
                ulonglong2 w0a = *(const ulonglong2*)wp;
                ulonglong2 w1a = *(const ulonglong2*)(wp + 128);
                float4 a0a = *(const float4*)ap;
                float4 a1a = *(const float4*)(ap + 4);
                #pragma unroll 2
                for (int k = 0; k < 96; k += 2) {
                    ulonglong2 w0b = *(const ulonglong2*)(wp + 256);
                    ulonglong2 w1b = *(const ulonglong2*)(wp + 384);
                    float4 a0b = *(const float4*)(ap + SA);
                    float4 a1b = *(const float4*)(ap + SA + 4);
                    l1_fma(acc, w0a, w1a, a0a, a1a);
                    w0a = *(const ulonglong2*)(wp + 512);   // overrun -> W2 region, safe
                    w1a = *(const ulonglong2*)(wp + 640);
                    a0a = *(const float4*)(ap + 2 * SA);
                    a1a = *(const float4*)(ap + 2 * SA + 4);
                    l1_fma(acc, w0b, w1b, a0b, a1b);
                    wp += 512; ap += 2 * SA;
                }

                float2 hv[8];
                #pragma unroll
                for (int b = 0; b < 8; b++)
                    cellup(acc[b][0], acc[b][1], acc[b][2], acc[b][3], c1s[b], hv[b]);

                // h1[s] -> write region rows 32+2jp, 33+2jp, cols 8*bt..
                float* hd = wrg + 32 * SA;
                int j0 = 2 * jp;
                *(float4*)&hd[j0 * SA + 8 * bt]           = make_float4(hv[0].x, hv[1].x, hv[2].x, hv[3].x);
                *(float4*)&hd[j0 * SA + 8 * bt + 4]       = make_float4(hv[4].x, hv[5].x, hv[6].x, hv[7].x);
                *(float4*)&hd[(j0 + 1) * SA + 8 * bt]     = make_float4(hv[0].y, hv[1].y, hv[2].y, hv[3].y);
                *(float4*)&hd[(j0 + 1) * SA + 8 * bt + 4] = make_float4(hv[4].y, hv[5].y, hv[6].y, hv[7].y);
            }
            __syncthreads();
        }
    } else {
        // ================= LAYER-2 warps (+ x prefetch) =================
        // Warp w owns j-pairs [4w, 4w+4); 8 lanes share a jp, splitting 32
        // batches into groups of 4. Weight row per warp-k = 4 distinct 16B = 64B.
        const int u = tid - 128;
        const int lane = u & 31;
        const int wd   = u >> 5;
        const int jp = wd * 4 + (lane >> 3);   // 0..15
        const int b0 = (lane & 7) * 4;         // batches b0 .. b0+3
        const int xb = u >> 2, xq = u & 3;
        const float* xg0 = x + ((size_t)(blockIdx.x * BB + xb) * TT) * 32 + xq * 8;
        uint64_t bias[4];
        {
            ulonglong2 b01 = *(const ulonglong2*)(sm + OFF_B2 + jp * 8);
            ulonglong2 b23 = *(const ulonglong2*)(sm + OFF_B2 + jp * 8 + 4);
            bias[0] = b01.x; bias[1] = b01.y; bias[2] = b23.x; bias[3] = b23.y;
        }
        uint64_t c2s[4] = {0,0,0,0};
        const float* wbase = sm + OFF_W2 + jp * 4;

        for (int s = 0; s <= TT; s++) {
            float4 pv0, pv1;
            const bool dopf = (s + 1 < TT);
            if (dopf) {
                const float* xg = xg0 + (size_t)(s + 1) * 32;
                pv0 = *(const float4*)xg;
                pv1 = *(const float4*)(xg + 4);
            }
            const float* rr = sm + OFF_R + (s & 1) * REGF;
            float* wrg = sm + OFF_R + ((s + 1) & 1) * REGF;

            if (s >= 1) {
                uint64_t acc[4][4];
                #pragma unroll
                for (int b = 0; b < 4; b++) {
                    acc[b][0] = bias[0]; acc[b][1] = bias[1];
                    acc[b][2] = bias[2]; acc[b][3] = bias[3];
                }
                // fused h1(s-1)+h2(s-2) stream, double-buffered
                const float* wp = wbase;
                const float* ap = rr + 32 * SA + b0;
                ulonglong2 w0a = *(const ulonglong2*)wp;
                ulonglong2 w1a = *(const ulonglong2*)(wp + 64);
                float4 a0a = *(const float4*)ap;
                #pragma unroll 2
                for (int k = 0; k < 96; k += 2) {
                    ulonglong2 w0b = *(const ulonglong2*)(wp + 128);
                    ulonglong2 w1b = *(const ulonglong2*)(wp + 192);
                    float4 a0b = *(const float4*)(ap + SA);
                    l2_fma(acc, w0a, w1a, a0a);
                    w0a = *(const ulonglong2*)(wp + 256);   // overrun safe
                    w1a = *(const ulonglong2*)(wp + 320);
                    a0a = *(const float4*)(ap + 2 * SA);
                    l2_fma(acc, w0b, w1b, a0b);
                    wp += 256; ap += 2 * SA;
                }

                float2 hv[4];
                #pragma unroll
                for (int b = 0; b < 4; b++)
                    cellup(acc[b][0], acc[b][1], acc[b][2], acc[b][3], c2s[b], hv[b]);

                // h2[s-1] -> write region rows 96+2jp, 97+2jp, cols b0..
                float* hd = wrg + 96 * SA;
                int j0 = 2 * jp;
                *(float4*)&hd[j0 * SA + b0]       = make_float4(hv[0].x, hv[1].x, hv[2].x, hv[3].x);
                *(float4*)&hd[(j0 + 1) * SA + b0] = make_float4(hv[0].y, hv[1].y, hv[2].y, hv[3].y);
            }
            if (dopf) {
                float* d = wrg;   // x(s+1) -> write region rows 0..31
                int f0 = xq * 8;
                float vv[8] = {pv0.x, pv0.y, pv0.z, pv0.w, pv1.x, pv1.y, pv1.z, pv1.w};
                #pragma unroll
                for (int c = 0; c < 8; c++) d[(f0 + c) * SA + xb] = vv[c];
            }
            __syncthreads();
        }
    }

    // ---- head: h2[T-1] in region 1, rows 96..127 ----
    if (tid < 96) {
        int b = tid / 3, n = tid % 3;
        const float* h2p = sm + OFF_R + REGF + 96 * SA;
        float accv = bhead[n];
        #pragma unroll
        for (int j = 0; j < 32; j++)
            accv += h2p[j * SA + b] * Whead[n * 32 + j];
        out[(size_t)(blockIdx.x * BB + b) * 3 + n] = accv;
    }
}

extern "C" void kernel_launch(void* const* d_in, const int* in_sizes, int n_in,
                              void* d_out, int out_size) {
    (void)in_sizes; (void)n_in; (void)out_size;
    const float* x     = (const float*)d_in[0];
    const float* Wih1  = (const float*)d_in[1];
    const float* Whh1  = (const float*)d_in[2];
    const float* bih1  = (const float*)d_in[3];
    const float* bhh1  = (const float*)d_in[4];
    const float* Wih2  = (const float*)d_in[5];
    const float* Whh2  = (const float*)d_in[6];
    const float* bih2  = (const float*)d_in[7];
    const float* bhh2  = (const float*)d_in[8];
    const float* Whead = (const float*)d_in[9];
    const float* bhead = (const float*)d_in[10];
    float* out = (float*)d_out;

    cudaFuncSetAttribute(lstm_pipe_kernel,
                         cudaFuncAttributeMaxDynamicSharedMemorySize, SMEM_BYTES);
    lstm_pipe_kernel<<<NBLK, NTHR, SMEM_BYTES>>>(
        x, Wih1, Whh1, bih1, bhh1, Wih2, Whh2, bih2, bhh2, Whead, bhead, out);
}